// round 1
// baseline (speedup 1.0000x reference)
#include <cuda_runtime.h>
#include <cuda_bf16.h>
#include <math.h>

// Problem constants (fixed instance)
#define BATCH 8
#define CIN   128
#define HH    128
#define WW    128
#define HWSZ  (HH*WW)          // 16384
#define NH    8
#define TCH   384               // pos output channels
#define QKVCH 384
#define YCH   256
#define GRAM_NS 16              // split-K partitions for gram

// ---------------- scratch (static device allocations) ----------------
__device__ float g_t   [(size_t)BATCH * TCH   * HWSZ];   // 201 MB
__device__ float g_qkv [(size_t)BATCH * QKVCH * HWSZ];   // 201 MB
__device__ float g_y   [(size_t)BATCH * YCH   * HWSZ];   // 134 MB
__device__ float g_Spart[GRAM_NS * 64 * 256];
__device__ float g_Npart[GRAM_NS * 64 * 32];
__device__ float g_attn [64 * 256];

// ---------------- SGEMM: C[M,N] = A[M,K] @ B[K,N] (+bias[M]) per batch -----
// BM=128 BN=128 BK=8 TM=8 TN=8, 256 threads
__global__ __launch_bounds__(256, 2)
void gemm_kernel(const float* __restrict__ A, const float* __restrict__ B,
                 const float* __restrict__ bias, float* __restrict__ C,
                 int M, int N, int K, long strideB, long strideC)
{
    constexpr int BM = 128, BN = 128, BK = 8, TM = 8, TN = 8;
    __shared__ __align__(16) float As[BK][BM + 4];
    __shared__ __align__(16) float Bs[BK][BN];

    const float* Bb = B + (long)blockIdx.z * strideB;
    float*       Cb = C + (long)blockIdx.z * strideC;
    const int m0 = blockIdx.y * BM;
    const int n0 = blockIdx.x * BN;
    const int tid = threadIdx.x;
    const int tx = tid & 15;   // 0..15 over N
    const int ty = tid >> 4;   // 0..15 over M

    float acc[TM][TN];
#pragma unroll
    for (int i = 0; i < TM; i++)
#pragma unroll
        for (int j = 0; j < TN; j++) acc[i][j] = 0.f;

    for (int k0 = 0; k0 < K; k0 += BK) {
        // A tile: BM x BK (1024 elems, 4/thread)
#pragma unroll
        for (int e = tid; e < BM * BK; e += 256) {
            int m = e >> 3, k = e & 7;
            As[k][m] = A[(long)(m0 + m) * K + k0 + k];
        }
        // B tile: BK x BN (1024 elems, 4/thread)
#pragma unroll
        for (int e = tid; e < BK * BN; e += 256) {
            int k = e >> 7, n = e & 127;
            Bs[k][n] = Bb[(long)(k0 + k) * N + n0 + n];
        }
        __syncthreads();
#pragma unroll
        for (int k = 0; k < BK; k++) {
            float4 a0 = *(const float4*)&As[k][ty * TM];
            float4 a1 = *(const float4*)&As[k][ty * TM + 4];
            float4 b0 = *(const float4*)&Bs[k][tx * TN];
            float4 b1 = *(const float4*)&Bs[k][tx * TN + 4];
            float ra[TM] = {a0.x, a0.y, a0.z, a0.w, a1.x, a1.y, a1.z, a1.w};
            float rb[TN] = {b0.x, b0.y, b0.z, b0.w, b1.x, b1.y, b1.z, b1.w};
#pragma unroll
            for (int i = 0; i < TM; i++)
#pragma unroll
                for (int j = 0; j < TN; j++)
                    acc[i][j] += ra[i] * rb[j];
        }
        __syncthreads();
    }
#pragma unroll
    for (int i = 0; i < TM; i++) {
        int m = m0 + ty * TM + i;
        float bv = bias ? bias[m] : 0.f;
        float4 o0 = make_float4(acc[i][0] + bv, acc[i][1] + bv, acc[i][2] + bv, acc[i][3] + bv);
        float4 o1 = make_float4(acc[i][4] + bv, acc[i][5] + bv, acc[i][6] + bv, acc[i][7] + bv);
        *(float4*)&Cb[(long)m * N + n0 + tx * TN]     = o0;
        *(float4*)&Cb[(long)m * N + n0 + tx * TN + 4] = o1;
    }
}

// ------------- grouped conv: 2 in-ch per out-ch, stride 1, SAME pad -------
// grid: (64 spatial tiles, OC, B); block: 256 (32x8 tile)
template<int KS, int PAD>
__global__ __launch_bounds__(256)
void gconv_kernel(const float* __restrict__ in, const float* __restrict__ w,
                  const float* __restrict__ bias, float* __restrict__ out,
                  int inC, int outCtot, int outOff)
{
    constexpr int TW = 32, TH = 8;
    constexpr int SW = TW + 2 * PAD, SH = TH + 2 * PAD;
    __shared__ float s[2][SH][SW];
    __shared__ float ws[2 * KS * KS];

    const int oc = blockIdx.y;
    const int b  = blockIdx.z;
    const int x0 = (blockIdx.x & 3) * TW;
    const int y0 = (blockIdx.x >> 2) * TH;
    const int tid = threadIdx.x;

    if (tid < 2 * KS * KS) ws[tid] = w[oc * 2 * KS * KS + tid];

    const float* inb = in + ((long)b * inC + 2 * oc) * HWSZ;
#pragma unroll
    for (int e = tid; e < 2 * SH * SW; e += 256) {
        int c = e / (SH * SW);
        int rem = e - c * (SH * SW);
        int sy = rem / SW, sx = rem - sy * SW;
        int gy = y0 + sy - PAD, gx = x0 + sx - PAD;
        float v = 0.f;
        if (gy >= 0 && gy < HH && gx >= 0 && gx < WW)
            v = inb[(long)c * HWSZ + gy * WW + gx];
        s[c][sy][sx] = v;
    }
    __syncthreads();

    const int px = tid & 31, py = tid >> 5;
    float acc = bias ? bias[oc] : 0.f;
#pragma unroll
    for (int c = 0; c < 2; c++)
#pragma unroll
        for (int ky = 0; ky < KS; ky++)
#pragma unroll
            for (int kx = 0; kx < KS; kx++)
                acc += s[c][py + ky][px + kx] * ws[(c * KS + ky) * KS + kx];

    out[((long)b * outCtot + outOff + oc) * HWSZ + (y0 + py) * WW + x0 + px] = acc;
}

// ---------------- gram partials: S[d,e] = q_d . k_e ; norms -----------------
// grid (GRAM_NS, 64 bh), 256 threads
__global__ __launch_bounds__(256)
void gram_partial(const float* __restrict__ qkv,
                  float* __restrict__ Spart, float* __restrict__ Npart)
{
    constexpr int CH = 64;
    __shared__ float qs[16][CH + 1];
    __shared__ float ks[16][CH + 1];
    const int bh = blockIdx.y, split = blockIdx.x;
    const int b = bh >> 3, h = bh & 7;
    const int tid = threadIdx.x;
    const int d = tid >> 4, e = tid & 15;

    const float* qbase = qkv + ((long)b * QKVCH + h * 16) * HWSZ;
    const float* kbase = qbase + 128L * HWSZ;
    const int nlen = HWSZ / GRAM_NS;       // 1024
    const int n0 = split * nlen;

    float sacc = 0.f, nacc = 0.f;
    for (int c0 = 0; c0 < nlen; c0 += CH) {
#pragma unroll
        for (int t2 = tid; t2 < 16 * CH; t2 += 256) {
            int r = t2 / CH, c = t2 - r * CH;
            qs[r][c] = qbase[(long)r * HWSZ + n0 + c0 + c];
            ks[r][c] = kbase[(long)r * HWSZ + n0 + c0 + c];
        }
        __syncthreads();
#pragma unroll 8
        for (int c = 0; c < CH; c++)
            sacc += qs[d][c] * ks[e][c];
        if (tid < 32) {
            const float* row = (tid < 16) ? &qs[tid][0] : &ks[tid - 16][0];
#pragma unroll 8
            for (int c = 0; c < CH; c++)
                nacc += row[c] * row[c];
        }
        __syncthreads();
    }
    Spart[((long)split * 64 + bh) * 256 + tid] = sacc;
    if (tid < 32)
        Npart[((long)split * 64 + bh) * 32 + tid] = nacc;
}

// ---------------- reduce + l2norm + temp + softmax -> attn ------------------
__global__ __launch_bounds__(256)
void softmax_kernel(const float* __restrict__ Spart, const float* __restrict__ Npart,
                    const float* __restrict__ temp, float* __restrict__ attn)
{
    const int bh = blockIdx.x;
    const int h = bh & 7;
    const int tid = threadIdx.x;
    __shared__ float nrm[32];

    float s = 0.f;
#pragma unroll
    for (int sp = 0; sp < GRAM_NS; sp++)
        s += Spart[((long)sp * 64 + bh) * 256 + tid];
    if (tid < 32) {
        float nn = 0.f;
#pragma unroll
        for (int sp = 0; sp < GRAM_NS; sp++)
            nn += Npart[((long)sp * 64 + bh) * 32 + tid];
        nrm[tid] = fmaxf(sqrtf(nn), 1e-12f);
    }
    __syncthreads();

    const int d = tid >> 4;
    float logit = s / (nrm[d] * nrm[16 + (tid & 15)]) * temp[h];

    float m = logit;
#pragma unroll
    for (int o = 8; o > 0; o >>= 1)
        m = fmaxf(m, __shfl_xor_sync(0xffffffffu, m, o, 16));
    float p = expf(logit - m);
    float sum = p;
#pragma unroll
    for (int o = 8; o > 0; o >>= 1)
        sum += __shfl_xor_sync(0xffffffffu, sum, o, 16);
    attn[bh * 256 + tid] = p / sum;
}

// ---------------- out = attn @ v -> y[0:128] --------------------------------
// grid (hw/256, NH, B), 256 threads
__global__ __launch_bounds__(256)
void attn_apply(const float* __restrict__ qkv, const float* __restrict__ attn,
                float* __restrict__ y)
{
    __shared__ float aw[256];
    __shared__ float vs[16][256];
    const int nc = blockIdx.x, h = blockIdx.y, b = blockIdx.z;
    const int tid = threadIdx.x;

    aw[tid] = attn[((b * 8 + h) * 256) + tid];
    const float* vbase = qkv + ((long)b * QKVCH + 256 + h * 16) * HWSZ + nc * 256;
#pragma unroll
    for (int e = 0; e < 16; e++)
        vs[e][tid] = vbase[(long)e * HWSZ + tid];
    __syncthreads();

    float* ybase = y + ((long)b * YCH + h * 16) * HWSZ + nc * 256 + tid;
#pragma unroll
    for (int d2 = 0; d2 < 16; d2++) {
        float acc = 0.f;
#pragma unroll
        for (int e = 0; e < 16; e++)
            acc += aw[d2 * 16 + e] * vs[e][tid];
        ybase[(long)d2 * HWSZ] = acc;
    }
}

// ---------------- launch ----------------------------------------------------
extern "C" void kernel_launch(void* const* d_in, const int* in_sizes, int n_in,
                              void* d_out, int out_size)
{
    const float* x      = (const float*)d_in[0];
    const float* pos_w  = (const float*)d_in[1];
    const float* pos_b  = (const float*)d_in[2];
    const float* qd3_w  = (const float*)d_in[3];
    const float* qd3_b  = (const float*)d_in[4];
    const float* qd5_w  = (const float*)d_in[5];
    const float* qd5_b  = (const float*)d_in[6];
    const float* temp   = (const float*)d_in[7];
    const float* d3_w   = (const float*)d_in[8];
    const float* d3_b   = (const float*)d_in[9];
    const float* d5_w   = (const float*)d_in[10];
    const float* d5_b   = (const float*)d_in[11];
    const float* proj_w = (const float*)d_in[12];
    float* out = (float*)d_out;

    float *t, *qkv, *y, *Spart, *Npart, *attn;
    cudaGetSymbolAddress((void**)&t,     g_t);
    cudaGetSymbolAddress((void**)&qkv,   g_qkv);
    cudaGetSymbolAddress((void**)&y,     g_y);
    cudaGetSymbolAddress((void**)&Spart, g_Spart);
    cudaGetSymbolAddress((void**)&Npart, g_Npart);
    cudaGetSymbolAddress((void**)&attn,  g_attn);

    // 1) t = pos_w @ x + pos_b   (M=384, K=128, N=hw per batch)
    {
        dim3 grid(HWSZ / 128, TCH / 128, BATCH);
        gemm_kernel<<<grid, 256>>>(pos_w, x, pos_b, t,
                                   TCH, HWSZ, CIN,
                                   (long)CIN * HWSZ, (long)TCH * HWSZ);
    }
    // 2) qkv[0:192]  = gconv3(t),  3) qkv[192:384] = gconv5(t)
    {
        dim3 grid(64, 192, BATCH);
        gconv_kernel<3, 1><<<grid, 256>>>(t, qd3_w, qd3_b, qkv, TCH, QKVCH, 0);
        gconv_kernel<5, 2><<<grid, 256>>>(t, qd5_w, qd5_b, qkv, TCH, QKVCH, 192);
    }
    // 4) gram partials, 5) softmax -> attn
    {
        dim3 grid(GRAM_NS, 64);
        gram_partial<<<grid, 256>>>(qkv, Spart, Npart);
        softmax_kernel<<<64, 256>>>(Spart, Npart, temp, attn);
    }
    // 6) y[0:128] = attn @ v
    {
        dim3 grid(HWSZ / 256, NH, BATCH);
        attn_apply<<<grid, 256>>>(qkv, attn, y);
    }
    // 7) y[128:192] = gconv3(x), 8) y[192:256] = gconv5(x)
    {
        dim3 grid(64, 64, BATCH);
        gconv_kernel<3, 1><<<grid, 256>>>(x, d3_w, d3_b, y, CIN, YCH, 128);
        gconv_kernel<5, 2><<<grid, 256>>>(x, d5_w, d5_b, y, CIN, YCH, 192);
    }
    // 9) out = proj_w @ y   (M=128, K=256, N=hw per batch, no bias)
    {
        dim3 grid(HWSZ / 128, CIN / 128, BATCH);
        gemm_kernel<<<grid, 256>>>(proj_w, y, nullptr, out,
                                   CIN, HWSZ, YCH,
                                   (long)YCH * HWSZ, (long)CIN * HWSZ);
    }
}

// round 2
// speedup vs baseline: 1.2880x; 1.2880x over previous
#include <cuda_runtime.h>
#include <cuda_bf16.h>
#include <math.h>

// Problem constants (fixed instance)
#define BATCH 8
#define CIN   128
#define HH    128
#define WW    128
#define HWSZ  (HH*WW)          // 16384
#define NH    8
#define TCH   384               // pos output channels
#define QKVCH 384
#define YCH   256
#define GRAM_NS 16              // split-K partitions for gram

// ---------------- scratch (static device allocations) ----------------
__device__ float g_t   [(size_t)BATCH * TCH   * HWSZ];   // 201 MB
__device__ float g_qkv [(size_t)BATCH * QKVCH * HWSZ];   // 201 MB
__device__ float g_y   [(size_t)BATCH * YCH   * HWSZ];   // 134 MB
__device__ float g_Spart[GRAM_NS * 64 * 256];
__device__ float g_Npart[GRAM_NS * 64 * 32];
__device__ float g_attn [64 * 256];

// ---------------- cp.async helpers -----------------------------------------
__device__ __forceinline__ void cp_async16(void* smem_dst, const void* gsrc) {
    unsigned saddr = (unsigned)__cvta_generic_to_shared(smem_dst);
    asm volatile("cp.async.cg.shared.global [%0], [%1], 16;\n" :: "r"(saddr), "l"(gsrc));
}
__device__ __forceinline__ void cp_async_commit() {
    asm volatile("cp.async.commit_group;\n");
}
__device__ __forceinline__ void cp_async_wait0() {
    asm volatile("cp.async.wait_group 0;\n");
}

// ---------------- SGEMM: C[M,N] = A[M,K] @ B[K,N] (+bias[M]) per batch -----
// BM=128 BN=128 BK=16 TM=8 TN=8, 256 threads, double-buffered
__global__ __launch_bounds__(256)
void gemm_kernel(const float* __restrict__ A, const float* __restrict__ B,
                 const float* __restrict__ bias, float* __restrict__ C,
                 int M, int N, int K, long strideB, long strideC)
{
    constexpr int BM = 128, BN = 128, BK = 16, TM = 8, TN = 8;
    __shared__ __align__(16) float As[2][BK][BM + 4];
    __shared__ __align__(16) float Bs[2][BK][BN];

    const float* Bb = B + (long)blockIdx.z * strideB;
    float*       Cb = C + (long)blockIdx.z * strideC;
    const int m0 = blockIdx.y * BM;
    const int n0 = blockIdx.x * BN;
    const int tid = threadIdx.x;
    const int tx = tid & 15;   // N
    const int ty = tid >> 4;   // M

    // A-load mapping: 512 float4 per tile, 2 per thread
    const int a_row0 = (tid * 2) >> 2;          // tile row of first float4
    const int a_c40  = (tid * 2) & 3;           // float4 col within row (0..3)
    // B-load mapping: 512 float4, 2 per thread
    const int b_k0i  = (tid * 2) >> 5;          // k row (0..15)
    const int b_n40  = (tid * 2) & 31;          // float4 col (0..31)

    float acc[TM][TN];
#pragma unroll
    for (int i = 0; i < TM; i++)
#pragma unroll
        for (int j = 0; j < TN; j++) acc[i][j] = 0.f;

    float4 areg[2];

    // ---- prologue: stage 0 ----
    {
        const int k0 = 0;
#pragma unroll
        for (int i = 0; i < 2; i++) {
            int idx = tid * 2 + i;
            int m = idx >> 2, c4 = idx & 3;
            areg[i] = *(const float4*)&A[(long)(m0 + m) * K + k0 + c4 * 4];
        }
#pragma unroll
        for (int i = 0; i < 2; i++) {
            int idx = tid * 2 + i;
            int k = idx >> 5, n4 = idx & 31;
            cp_async16(&Bs[0][k][n4 * 4], &Bb[(long)(k0 + k) * N + n0 + n4 * 4]);
        }
        cp_async_commit();
#pragma unroll
        for (int i = 0; i < 2; i++) {
            int idx = tid * 2 + i;
            int m = idx >> 2, c4 = idx & 3;
            As[0][c4 * 4 + 0][m] = areg[i].x;
            As[0][c4 * 4 + 1][m] = areg[i].y;
            As[0][c4 * 4 + 2][m] = areg[i].z;
            As[0][c4 * 4 + 3][m] = areg[i].w;
        }
        cp_async_wait0();
        __syncthreads();
    }

    int buf = 0;
    for (int k0 = 0; k0 < K; k0 += BK) {
        const int nxt = k0 + BK;
        const bool more = nxt < K;
        if (more) {
#pragma unroll
            for (int i = 0; i < 2; i++) {
                int idx = tid * 2 + i;
                int m = idx >> 2, c4 = idx & 3;
                areg[i] = *(const float4*)&A[(long)(m0 + m) * K + nxt + c4 * 4];
            }
#pragma unroll
            for (int i = 0; i < 2; i++) {
                int idx = tid * 2 + i;
                int k = idx >> 5, n4 = idx & 31;
                cp_async16(&Bs[buf ^ 1][k][n4 * 4], &Bb[(long)(nxt + k) * N + n0 + n4 * 4]);
            }
            cp_async_commit();
        }

#pragma unroll
        for (int k = 0; k < BK; k++) {
            float4 a0 = *(const float4*)&As[buf][k][ty * TM];
            float4 a1 = *(const float4*)&As[buf][k][ty * TM + 4];
            float4 b0 = *(const float4*)&Bs[buf][k][tx * TN];
            float4 b1 = *(const float4*)&Bs[buf][k][tx * TN + 4];
            float ra[TM] = {a0.x, a0.y, a0.z, a0.w, a1.x, a1.y, a1.z, a1.w};
            float rb[TN] = {b0.x, b0.y, b0.z, b0.w, b1.x, b1.y, b1.z, b1.w};
#pragma unroll
            for (int i = 0; i < TM; i++)
#pragma unroll
                for (int j = 0; j < TN; j++)
                    acc[i][j] += ra[i] * rb[j];
        }

        if (more) {
#pragma unroll
            for (int i = 0; i < 2; i++) {
                int idx = tid * 2 + i;
                int m = idx >> 2, c4 = idx & 3;
                As[buf ^ 1][c4 * 4 + 0][m] = areg[i].x;
                As[buf ^ 1][c4 * 4 + 1][m] = areg[i].y;
                As[buf ^ 1][c4 * 4 + 2][m] = areg[i].z;
                As[buf ^ 1][c4 * 4 + 3][m] = areg[i].w;
            }
            cp_async_wait0();
        }
        __syncthreads();
        buf ^= 1;
    }

#pragma unroll
    for (int i = 0; i < TM; i++) {
        int m = m0 + ty * TM + i;
        float bv = bias ? bias[m] : 0.f;
        float4 o0 = make_float4(acc[i][0] + bv, acc[i][1] + bv, acc[i][2] + bv, acc[i][3] + bv);
        float4 o1 = make_float4(acc[i][4] + bv, acc[i][5] + bv, acc[i][6] + bv, acc[i][7] + bv);
        *(float4*)&Cb[(long)m * N + n0 + tx * TN]     = o0;
        *(float4*)&Cb[(long)m * N + n0 + tx * TN + 4] = o1;
    }
}

// ------------- fused grouped conv: per group compute BOTH 3x3 and 5x5 ------
// group g reads in[2g], in[2g+1]; writes out[off3+g] (3x3) and out[off5+g] (5x5)
// grid: (64 spatial tiles, groups, B); block 256 (32x8 output tile)
__global__ __launch_bounds__(256)
void gconv_fused_kernel(const float* __restrict__ in,
                        const float* __restrict__ w3, const float* __restrict__ b3,
                        const float* __restrict__ w5, const float* __restrict__ b5,
                        float* __restrict__ out,
                        int inC, int outCtot, int off3, int off5)
{
    constexpr int TW = 32, TH = 8, PAD = 2;
    constexpr int SW = TW + 2 * PAD, SH = TH + 2 * PAD;   // 36 x 12
    __shared__ float s[2][SH][SW];
    __shared__ float ws3[18];
    __shared__ float ws5[50];

    const int g  = blockIdx.y;
    const int b  = blockIdx.z;
    const int x0 = (blockIdx.x & 3) * TW;
    const int y0 = (blockIdx.x >> 2) * TH;
    const int tid = threadIdx.x;

    if (tid < 18) ws3[tid] = w3[g * 18 + tid];
    else if (tid < 68) ws5[tid - 18] = w5[g * 50 + (tid - 18)];

    const float* inb = in + ((long)b * inC + 2 * g) * HWSZ;
#pragma unroll
    for (int e = tid; e < 2 * SH * SW; e += 256) {
        int c = e / (SH * SW);
        int rem = e - c * (SH * SW);
        int sy = rem / SW, sx = rem - sy * SW;
        int gy = y0 + sy - PAD, gx = x0 + sx - PAD;
        float v = 0.f;
        if (gy >= 0 && gy < HH && gx >= 0 && gx < WW)
            v = inb[(long)c * HWSZ + gy * WW + gx];
        s[c][sy][sx] = v;
    }
    __syncthreads();

    const int px = tid & 31, py = tid >> 5;
    float acc3 = b3[g];
    float acc5 = b5[g];
#pragma unroll
    for (int c = 0; c < 2; c++) {
#pragma unroll
        for (int ky = 0; ky < 5; ky++)
#pragma unroll
            for (int kx = 0; kx < 5; kx++) {
                float v = s[c][py + ky][px + kx];
                acc5 += v * ws5[(c * 5 + ky) * 5 + kx];
                if (ky >= 1 && ky <= 3 && kx >= 1 && kx <= 3)
                    acc3 += v * ws3[(c * 3 + (ky - 1)) * 3 + (kx - 1)];
            }
    }

    const long sp = (long)(y0 + py) * WW + x0 + px;
    out[((long)b * outCtot + off3 + g) * HWSZ + sp] = acc3;
    out[((long)b * outCtot + off5 + g) * HWSZ + sp] = acc5;
}

// ---------------- gram partials: S[d,e] = q_d . k_e ; norms -----------------
// grid (GRAM_NS, 64 bh), 256 threads; float4 smem compute
__global__ __launch_bounds__(256)
void gram_partial(const float* __restrict__ qkv,
                  float* __restrict__ Spart, float* __restrict__ Npart)
{
    constexpr int CH = 64;
    __shared__ __align__(16) float qs[16][CH + 4];
    __shared__ __align__(16) float ks[16][CH + 4];
    const int bh = blockIdx.y, split = blockIdx.x;
    const int b = bh >> 3, h = bh & 7;
    const int tid = threadIdx.x;
    const int d = tid >> 4, e = tid & 15;

    const float* qbase = qkv + ((long)b * QKVCH + h * 16) * HWSZ;
    const float* kbase = qbase + 128L * HWSZ;
    const int nlen = HWSZ / GRAM_NS;       // 1024
    const int n0 = split * nlen;

    const int lr = tid >> 4;   // row 0..15
    const int lc = tid & 15;   // float4 col 0..15

    float sacc = 0.f, nacc = 0.f;
    for (int c0 = 0; c0 < nlen; c0 += CH) {
        *(float4*)&qs[lr][lc * 4] = *(const float4*)&qbase[(long)lr * HWSZ + n0 + c0 + lc * 4];
        *(float4*)&ks[lr][lc * 4] = *(const float4*)&kbase[(long)lr * HWSZ + n0 + c0 + lc * 4];
        __syncthreads();
#pragma unroll
        for (int c4 = 0; c4 < CH / 4; c4++) {
            float4 qa = *(const float4*)&qs[d][c4 * 4];
            float4 kb = *(const float4*)&ks[e][c4 * 4];
            sacc += qa.x * kb.x + qa.y * kb.y + qa.z * kb.z + qa.w * kb.w;
        }
        if (tid < 32) {
            const float* row = (tid < 16) ? &qs[tid][0] : &ks[tid - 16][0];
#pragma unroll
            for (int c4 = 0; c4 < CH / 4; c4++) {
                float4 r = *(const float4*)&row[c4 * 4];
                nacc += r.x * r.x + r.y * r.y + r.z * r.z + r.w * r.w;
            }
        }
        __syncthreads();
    }
    Spart[((long)split * 64 + bh) * 256 + tid] = sacc;
    if (tid < 32)
        Npart[((long)split * 64 + bh) * 32 + tid] = nacc;
}

// ---------------- reduce + l2norm + temp + softmax -> attn ------------------
__global__ __launch_bounds__(256)
void softmax_kernel(const float* __restrict__ Spart, const float* __restrict__ Npart,
                    const float* __restrict__ temp, float* __restrict__ attn)
{
    const int bh = blockIdx.x;
    const int h = bh & 7;
    const int tid = threadIdx.x;
    __shared__ float nrm[32];

    float s = 0.f;
#pragma unroll
    for (int sp = 0; sp < GRAM_NS; sp++)
        s += Spart[((long)sp * 64 + bh) * 256 + tid];
    if (tid < 32) {
        float nn = 0.f;
#pragma unroll
        for (int sp = 0; sp < GRAM_NS; sp++)
            nn += Npart[((long)sp * 64 + bh) * 32 + tid];
        nrm[tid] = fmaxf(sqrtf(nn), 1e-12f);
    }
    __syncthreads();

    const int d = tid >> 4;
    float logit = s / (nrm[d] * nrm[16 + (tid & 15)]) * temp[h];

    float m = logit;
#pragma unroll
    for (int o = 8; o > 0; o >>= 1)
        m = fmaxf(m, __shfl_xor_sync(0xffffffffu, m, o, 16));
    float p = expf(logit - m);
    float sum = p;
#pragma unroll
    for (int o = 8; o > 0; o >>= 1)
        sum += __shfl_xor_sync(0xffffffffu, sum, o, 16);
    attn[bh * 256 + tid] = p / sum;
}

// ---------------- out = attn @ v -> y[0:128] --------------------------------
// grid (hw/256, NH, B), 256 threads; v held in registers
__global__ __launch_bounds__(256)
void attn_apply(const float* __restrict__ qkv, const float* __restrict__ attn,
                float* __restrict__ y)
{
    __shared__ float aw[256];
    const int nc = blockIdx.x, h = blockIdx.y, b = blockIdx.z;
    const int tid = threadIdx.x;

    aw[tid] = attn[((b * 8 + h) * 256) + tid];
    const float* vbase = qkv + ((long)b * QKVCH + 256 + h * 16) * HWSZ + nc * 256;
    float vreg[16];
#pragma unroll
    for (int e = 0; e < 16; e++)
        vreg[e] = vbase[(long)e * HWSZ + tid];
    __syncthreads();

    float* ybase = y + ((long)b * YCH + h * 16) * HWSZ + nc * 256 + tid;
#pragma unroll
    for (int d2 = 0; d2 < 16; d2++) {
        float acc = 0.f;
#pragma unroll
        for (int e = 0; e < 16; e++)
            acc += aw[d2 * 16 + e] * vreg[e];
        ybase[(long)d2 * HWSZ] = acc;
    }
}

// ---------------- launch ----------------------------------------------------
extern "C" void kernel_launch(void* const* d_in, const int* in_sizes, int n_in,
                              void* d_out, int out_size)
{
    const float* x      = (const float*)d_in[0];
    const float* pos_w  = (const float*)d_in[1];
    const float* pos_b  = (const float*)d_in[2];
    const float* qd3_w  = (const float*)d_in[3];
    const float* qd3_b  = (const float*)d_in[4];
    const float* qd5_w  = (const float*)d_in[5];
    const float* qd5_b  = (const float*)d_in[6];
    const float* temp   = (const float*)d_in[7];
    const float* d3_w   = (const float*)d_in[8];
    const float* d3_b   = (const float*)d_in[9];
    const float* d5_w   = (const float*)d_in[10];
    const float* d5_b   = (const float*)d_in[11];
    const float* proj_w = (const float*)d_in[12];
    float* out = (float*)d_out;

    float *t, *qkv, *y, *Spart, *Npart, *attn;
    cudaGetSymbolAddress((void**)&t,     g_t);
    cudaGetSymbolAddress((void**)&qkv,   g_qkv);
    cudaGetSymbolAddress((void**)&y,     g_y);
    cudaGetSymbolAddress((void**)&Spart, g_Spart);
    cudaGetSymbolAddress((void**)&Npart, g_Npart);
    cudaGetSymbolAddress((void**)&attn,  g_attn);

    // 1) t = pos_w @ x + pos_b   (M=384, K=128, N=hw per batch)
    {
        dim3 grid(HWSZ / 128, TCH / 128, BATCH);
        gemm_kernel<<<grid, 256>>>(pos_w, x, pos_b, t,
                                   TCH, HWSZ, CIN,
                                   (long)CIN * HWSZ, (long)TCH * HWSZ);
    }
    // 2+3) qkv[0:192] = gconv3(t), qkv[192:384] = gconv5(t)  (fused, one read of t)
    {
        dim3 grid(64, 192, BATCH);
        gconv_fused_kernel<<<grid, 256>>>(t, qd3_w, qd3_b, qd5_w, qd5_b,
                                          qkv, TCH, QKVCH, 0, 192);
    }
    // 4) gram partials, 5) softmax -> attn
    {
        dim3 grid(GRAM_NS, 64);
        gram_partial<<<grid, 256>>>(qkv, Spart, Npart);
        softmax_kernel<<<64, 256>>>(Spart, Npart, temp, attn);
    }
    // 6) y[0:128] = attn @ v
    {
        dim3 grid(HWSZ / 256, NH, BATCH);
        attn_apply<<<grid, 256>>>(qkv, attn, y);
    }
    // 7+8) y[128:192] = gconv3(x), y[192:256] = gconv5(x)  (fused, one read of x)
    {
        dim3 grid(64, 64, BATCH);
        gconv_fused_kernel<<<grid, 256>>>(x, d3_w, d3_b, d5_w, d5_b,
                                          y, CIN, YCH, 128, 192);
    }
    // 9) out = proj_w @ y   (M=128, K=256, N=hw per batch, no bias)
    {
        dim3 grid(HWSZ / 128, CIN / 128, BATCH);
        gemm_kernel<<<grid, 256>>>(proj_w, y, nullptr, out,
                                   CIN, HWSZ, YCH,
                                   (long)YCH * HWSZ, (long)CIN * HWSZ);
    }
}

// round 5
// speedup vs baseline: 1.8042x; 1.4008x over previous
#include <cuda_runtime.h>
#include <cuda_bf16.h>
#include <math.h>
#include <stdint.h>

// Problem constants (fixed instance)
#define BATCH 8
#define CIN   128
#define HH    128
#define WW    128
#define HWSZ  (HH*WW)          // 16384
#define NH    8
#define TCH   384
#define QKVCH 384
#define YCH   256
#define GRAM_NS 16

// ---------------- scratch ----------------
__device__ float g_t   [(size_t)BATCH * TCH   * HWSZ];
__device__ float g_qkv [(size_t)BATCH * QKVCH * HWSZ];
__device__ float g_y   [(size_t)BATCH * YCH   * HWSZ];
__device__ float g_Spart[GRAM_NS * 64 * 256];
__device__ float g_Npart[GRAM_NS * 64 * 32];
__device__ float g_attn [64 * 256];

__device__ __forceinline__ uint32_t smem_u32(const void* p) {
    uint32_t a;
    asm("{ .reg .u64 t; cvta.to.shared.u64 t, %1; cvt.u32.u64 %0, t; }" : "=r"(a) : "l"(p));
    return a;
}
// pack two floats' bf16-rounded values: lo half = v0, hi half = v1
__device__ __forceinline__ uint32_t pack_bf16x2(float v0, float v1) {
    uint32_t r;
    asm("cvt.rn.bf16x2.f32 %0, %1, %2;" : "=r"(r) : "f"(v1), "f"(v0));
    return r;
}
__device__ __forceinline__ float bf16_hi_f(float v) {
    // value of v rounded to bf16, as float
    __nv_bfloat16 h = __float2bfloat16_rn(v);
    return __bfloat162float(h);
}

#define LDSM_X4(r0,r1,r2,r3,addr) \
    asm volatile("ldmatrix.sync.aligned.m8n8.x4.shared.b16 {%0,%1,%2,%3}, [%4];" \
        : "=r"(r0),"=r"(r1),"=r"(r2),"=r"(r3) : "r"(addr))
#define LDSM_X4_T(r0,r1,r2,r3,addr) \
    asm volatile("ldmatrix.sync.aligned.m8n8.x4.trans.shared.b16 {%0,%1,%2,%3}, [%4];" \
        : "=r"(r0),"=r"(r1),"=r"(r2),"=r"(r3) : "r"(addr))
#define MMA_BF16(c0,c1,c2,c3,a0,a1,a2,a3,b0,b1) \
    asm volatile("mma.sync.aligned.m16n8k16.row.col.f32.bf16.bf16.f32 " \
        "{%0,%1,%2,%3}, {%4,%5,%6,%7}, {%8,%9}, {%0,%1,%2,%3};" \
        : "+f"(c0),"+f"(c1),"+f"(c2),"+f"(c3) \
        : "r"(a0),"r"(a1),"r"(a2),"r"(a3),"r"(b0),"r"(b1))

// smem layout (bytes):
//  As_hi: 128 rows * 80B   = 10240
//  As_lo: +10240
//  Bs_hi: 32 rows * 272B   =  8704  at +20480
//  Bs_lo: +8704            at +29184 ; total 37888
#define A_STRIDE 80
#define B_STRIDE 272
#define SM_AL 10240
#define SM_BH 20480
#define SM_BL 29184
#define SM_TOTAL 37888

// ---------------- bf16-split tensor-core GEMM: C = A[M,K] @ B[K,N] (+bias) --
__global__ __launch_bounds__(256, 2)
void mma_gemm(const float* __restrict__ A, const float* __restrict__ B,
              const float* __restrict__ bias, float* __restrict__ C,
              int M, int N, int K, long strideB, long strideC)
{
    __shared__ __align__(16) uint8_t smem[SM_TOTAL];
    const uint32_t sb = smem_u32(smem);

    const int tid = threadIdx.x, wid = tid >> 5, lid = tid & 31;
    const int m0 = blockIdx.y * 128, n0 = blockIdx.x * 128;
    const float* Bb = B + (long)blockIdx.z * strideB;
    float*       Cb = C + (long)blockIdx.z * strideC;
    const int wm = (wid >> 2) * 64;   // warp m offset (0/64)
    const int wn = (wid & 3) * 32;    // warp n offset

    float acc[4][4][4];
#pragma unroll
    for (int i = 0; i < 4; i++)
#pragma unroll
        for (int j = 0; j < 4; j++)
#pragma unroll
            for (int r = 0; r < 4; r++) acc[i][j][r] = 0.f;

    const int lr = lid & 15, lc = lid >> 4;  // ldmatrix lane row / matrix-half

    for (int k0 = 0; k0 < K; k0 += 32) {
        // ---- global loads (before sync: overlap with previous MMA) ----
        float4 av[4]; int am[4], ac[4];
#pragma unroll
        for (int i = 0; i < 4; i++) {
            int idx = tid + i * 256;
            am[i] = idx >> 3; ac[i] = idx & 7;
            av[i] = *(const float4*)&A[(long)(m0 + am[i]) * K + k0 + ac[i] * 4];
        }
        float4 bv[4]; int bk[4], bc[4];
#pragma unroll
        for (int i = 0; i < 4; i++) {
            int idx = tid + i * 256;
            bk[i] = idx >> 5; bc[i] = idx & 31;
            bv[i] = *(const float4*)&Bb[(long)(k0 + bk[i]) * N + n0 + bc[i] * 4];
        }
        __syncthreads();   // prior iteration's ldmatrix done
        // ---- convert + store ----
#pragma unroll
        for (int i = 0; i < 4; i++) {
            float hx = bf16_hi_f(av[i].x), hy = bf16_hi_f(av[i].y);
            float hz = bf16_hi_f(av[i].z), hw = bf16_hi_f(av[i].w);
            uint32_t h0 = pack_bf16x2(hx, hy), h1 = pack_bf16x2(hz, hw);
            uint32_t l0 = pack_bf16x2(av[i].x - hx, av[i].y - hy);
            uint32_t l1 = pack_bf16x2(av[i].z - hz, av[i].w - hw);
            uint32_t off = sb + am[i] * A_STRIDE + ac[i] * 8;
            asm volatile("st.shared.v2.b32 [%0], {%1,%2};" :: "r"(off), "r"(h0), "r"(h1) : "memory");
            asm volatile("st.shared.v2.b32 [%0], {%1,%2};" :: "r"(off + SM_AL), "r"(l0), "r"(l1) : "memory");
        }
#pragma unroll
        for (int i = 0; i < 4; i++) {
            float hx = bf16_hi_f(bv[i].x), hy = bf16_hi_f(bv[i].y);
            float hz = bf16_hi_f(bv[i].z), hw = bf16_hi_f(bv[i].w);
            uint32_t h0 = pack_bf16x2(hx, hy), h1 = pack_bf16x2(hz, hw);
            uint32_t l0 = pack_bf16x2(bv[i].x - hx, bv[i].y - hy);
            uint32_t l1 = pack_bf16x2(bv[i].z - hz, bv[i].w - hw);
            uint32_t off = sb + SM_BH + bk[i] * B_STRIDE + bc[i] * 8;
            asm volatile("st.shared.v2.b32 [%0], {%1,%2};" :: "r"(off), "r"(h0), "r"(h1) : "memory");
            asm volatile("st.shared.v2.b32 [%0], {%1,%2};" :: "r"(off + 8704), "r"(l0), "r"(l1) : "memory");
        }
        __syncthreads();

        // ---- 2 k16 sub-steps ----
#pragma unroll
        for (int ks = 0; ks < 32; ks += 16) {
            uint32_t ah[4][4], bh[2][4], bl[2][4];
#pragma unroll
            for (int mt = 0; mt < 4; mt++) {
                uint32_t addr = sb + (wm + mt * 16 + lr) * A_STRIDE + (ks + lc * 8) * 2;
                LDSM_X4(ah[mt][0], ah[mt][1], ah[mt][2], ah[mt][3], addr);
            }
#pragma unroll
            for (int nt2 = 0; nt2 < 2; nt2++) {
                uint32_t addr = sb + SM_BH + (ks + lr) * B_STRIDE + (wn + nt2 * 16 + lc * 8) * 2;
                LDSM_X4_T(bh[nt2][0], bh[nt2][1], bh[nt2][2], bh[nt2][3], addr);
                LDSM_X4_T(bl[nt2][0], bl[nt2][1], bl[nt2][2], bl[nt2][3], addr + 8704);
            }
            // Ah*Bh and Ah*Bl
#pragma unroll
            for (int mt = 0; mt < 4; mt++)
#pragma unroll
                for (int nt = 0; nt < 4; nt++) {
                    uint32_t b0 = bh[nt >> 1][(nt & 1) * 2], b1 = bh[nt >> 1][(nt & 1) * 2 + 1];
                    MMA_BF16(acc[mt][nt][0], acc[mt][nt][1], acc[mt][nt][2], acc[mt][nt][3],
                             ah[mt][0], ah[mt][1], ah[mt][2], ah[mt][3], b0, b1);
                    uint32_t c0 = bl[nt >> 1][(nt & 1) * 2], c1 = bl[nt >> 1][(nt & 1) * 2 + 1];
                    MMA_BF16(acc[mt][nt][0], acc[mt][nt][1], acc[mt][nt][2], acc[mt][nt][3],
                             ah[mt][0], ah[mt][1], ah[mt][2], ah[mt][3], c0, c1);
                }
            // Al*Bh (load Al per m-tile to cap register pressure)
#pragma unroll
            for (int mt = 0; mt < 4; mt++) {
                uint32_t a0, a1, a2, a3;
                uint32_t addr = sb + SM_AL + (wm + mt * 16 + lr) * A_STRIDE + (ks + lc * 8) * 2;
                LDSM_X4(a0, a1, a2, a3, addr);
#pragma unroll
                for (int nt = 0; nt < 4; nt++) {
                    uint32_t b0 = bh[nt >> 1][(nt & 1) * 2], b1 = bh[nt >> 1][(nt & 1) * 2 + 1];
                    MMA_BF16(acc[mt][nt][0], acc[mt][nt][1], acc[mt][nt][2], acc[mt][nt][3],
                             a0, a1, a2, a3, b0, b1);
                }
            }
        }
    }

    // ---- epilogue: direct stores, float2 per (m, n-pair) ----
    const int erow = lid >> 2, ecol = (lid & 3) * 2;
#pragma unroll
    for (int mt = 0; mt < 4; mt++) {
        int m = m0 + wm + mt * 16 + erow;
        float bv0 = bias ? bias[m] : 0.f;
        float bv8 = bias ? bias[m + 8] : 0.f;
#pragma unroll
        for (int nt = 0; nt < 4; nt++) {
            int n = n0 + wn + nt * 8 + ecol;
            *(float2*)&Cb[(long)m * N + n] =
                make_float2(acc[mt][nt][0] + bv0, acc[mt][nt][1] + bv0);
            *(float2*)&Cb[(long)(m + 8) * N + n] =
                make_float2(acc[mt][nt][2] + bv8, acc[mt][nt][3] + bv8);
        }
    }
}

// ------------- fused grouped conv (3x3 + 5x5 per group) --------------------
__global__ __launch_bounds__(256)
void gconv_fused_kernel(const float* __restrict__ in,
                        const float* __restrict__ w3, const float* __restrict__ b3,
                        const float* __restrict__ w5, const float* __restrict__ b5,
                        float* __restrict__ out,
                        int inC, int outCtot, int off3, int off5)
{
    constexpr int TW = 32, TH = 8, PAD = 2;
    constexpr int SW = TW + 2 * PAD, SH = TH + 2 * PAD;
    __shared__ float s[2][SH][SW];
    __shared__ float ws3[18];
    __shared__ float ws5[50];

    const int g  = blockIdx.y;
    const int b  = blockIdx.z;
    const int x0 = (blockIdx.x & 3) * TW;
    const int y0 = (blockIdx.x >> 2) * TH;
    const int tid = threadIdx.x;

    if (tid < 18) ws3[tid] = w3[g * 18 + tid];
    else if (tid < 68) ws5[tid - 18] = w5[g * 50 + (tid - 18)];

    const float* inb = in + ((long)b * inC + 2 * g) * HWSZ;
#pragma unroll
    for (int e = tid; e < 2 * SH * SW; e += 256) {
        int c = e / (SH * SW);
        int rem = e - c * (SH * SW);
        int sy = rem / SW, sx = rem - sy * SW;
        int gy = y0 + sy - PAD, gx = x0 + sx - PAD;
        float v = 0.f;
        if (gy >= 0 && gy < HH && gx >= 0 && gx < WW)
            v = inb[(long)c * HWSZ + gy * WW + gx];
        s[c][sy][sx] = v;
    }
    __syncthreads();

    const int px = tid & 31, py = tid >> 5;
    float acc3 = b3[g];
    float acc5 = b5[g];
#pragma unroll
    for (int c = 0; c < 2; c++) {
#pragma unroll
        for (int ky = 0; ky < 5; ky++)
#pragma unroll
            for (int kx = 0; kx < 5; kx++) {
                float v = s[c][py + ky][px + kx];
                acc5 += v * ws5[(c * 5 + ky) * 5 + kx];
                if (ky >= 1 && ky <= 3 && kx >= 1 && kx <= 3)
                    acc3 += v * ws3[(c * 3 + (ky - 1)) * 3 + (kx - 1)];
            }
    }
    const long sp = (long)(y0 + py) * WW + x0 + px;
    out[((long)b * outCtot + off3 + g) * HWSZ + sp] = acc3;
    out[((long)b * outCtot + off5 + g) * HWSZ + sp] = acc5;
}

// ---------------- gram partials ---------------------------------------------
__global__ __launch_bounds__(256)
void gram_partial(const float* __restrict__ qkv,
                  float* __restrict__ Spart, float* __restrict__ Npart)
{
    constexpr int CH = 64;
    __shared__ __align__(16) float qs[16][CH + 4];
    __shared__ __align__(16) float ks[16][CH + 4];
    const int bh = blockIdx.y, split = blockIdx.x;
    const int b = bh >> 3, h = bh & 7;
    const int tid = threadIdx.x;
    const int d = tid >> 4, e = tid & 15;

    const float* qbase = qkv + ((long)b * QKVCH + h * 16) * HWSZ;
    const float* kbase = qbase + 128L * HWSZ;
    const int nlen = HWSZ / GRAM_NS;
    const int n0 = split * nlen;
    const int lr = tid >> 4, lc = tid & 15;

    float sacc = 0.f, nacc = 0.f;
    for (int c0 = 0; c0 < nlen; c0 += CH) {
        *(float4*)&qs[lr][lc * 4] = *(const float4*)&qbase[(long)lr * HWSZ + n0 + c0 + lc * 4];
        *(float4*)&ks[lr][lc * 4] = *(const float4*)&kbase[(long)lr * HWSZ + n0 + c0 + lc * 4];
        __syncthreads();
#pragma unroll
        for (int c4 = 0; c4 < CH / 4; c4++) {
            float4 qa = *(const float4*)&qs[d][c4 * 4];
            float4 kb = *(const float4*)&ks[e][c4 * 4];
            sacc += qa.x * kb.x + qa.y * kb.y + qa.z * kb.z + qa.w * kb.w;
        }
        if (tid < 32) {
            const float* row = (tid < 16) ? &qs[tid][0] : &ks[tid - 16][0];
#pragma unroll
            for (int c4 = 0; c4 < CH / 4; c4++) {
                float4 r = *(const float4*)&row[c4 * 4];
                nacc += r.x * r.x + r.y * r.y + r.z * r.z + r.w * r.w;
            }
        }
        __syncthreads();
    }
    Spart[((long)split * 64 + bh) * 256 + tid] = sacc;
    if (tid < 32)
        Npart[((long)split * 64 + bh) * 32 + tid] = nacc;
}

// ---------------- softmax ----------------------------------------------------
__global__ __launch_bounds__(256)
void softmax_kernel(const float* __restrict__ Spart, const float* __restrict__ Npart,
                    const float* __restrict__ temp, float* __restrict__ attn)
{
    const int bh = blockIdx.x;
    const int h = bh & 7;
    const int tid = threadIdx.x;
    __shared__ float nrm[32];

    float s = 0.f;
#pragma unroll
    for (int sp = 0; sp < GRAM_NS; sp++)
        s += Spart[((long)sp * 64 + bh) * 256 + tid];
    if (tid < 32) {
        float nn = 0.f;
#pragma unroll
        for (int sp = 0; sp < GRAM_NS; sp++)
            nn += Npart[((long)sp * 64 + bh) * 32 + tid];
        nrm[tid] = fmaxf(sqrtf(nn), 1e-12f);
    }
    __syncthreads();

    const int d = tid >> 4;
    float logit = s / (nrm[d] * nrm[16 + (tid & 15)]) * temp[h];
    float m = logit;
#pragma unroll
    for (int o = 8; o > 0; o >>= 1)
        m = fmaxf(m, __shfl_xor_sync(0xffffffffu, m, o, 16));
    float p = expf(logit - m);
    float sum = p;
#pragma unroll
    for (int o = 8; o > 0; o >>= 1)
        sum += __shfl_xor_sync(0xffffffffu, sum, o, 16);
    attn[bh * 256 + tid] = p / sum;
}

// ---------------- attn apply -------------------------------------------------
__global__ __launch_bounds__(256)
void attn_apply(const float* __restrict__ qkv, const float* __restrict__ attn,
                float* __restrict__ y)
{
    __shared__ float aw[256];
    const int nc = blockIdx.x, h = blockIdx.y, b = blockIdx.z;
    const int tid = threadIdx.x;

    aw[tid] = attn[((b * 8 + h) * 256) + tid];
    const float* vbase = qkv + ((long)b * QKVCH + 256 + h * 16) * HWSZ + nc * 256;
    float vreg[16];
#pragma unroll
    for (int e = 0; e < 16; e++)
        vreg[e] = vbase[(long)e * HWSZ + tid];
    __syncthreads();

    float* ybase = y + ((long)b * YCH + h * 16) * HWSZ + nc * 256 + tid;
#pragma unroll
    for (int d2 = 0; d2 < 16; d2++) {
        float acc = 0.f;
#pragma unroll
        for (int e = 0; e < 16; e++)
            acc += aw[d2 * 16 + e] * vreg[e];
        ybase[(long)d2 * HWSZ] = acc;
    }
}

// ---------------- launch -----------------------------------------------------
extern "C" void kernel_launch(void* const* d_in, const int* in_sizes, int n_in,
                              void* d_out, int out_size)
{
    const float* x      = (const float*)d_in[0];
    const float* pos_w  = (const float*)d_in[1];
    const float* pos_b  = (const float*)d_in[2];
    const float* qd3_w  = (const float*)d_in[3];
    const float* qd3_b  = (const float*)d_in[4];
    const float* qd5_w  = (const float*)d_in[5];
    const float* qd5_b  = (const float*)d_in[6];
    const float* temp   = (const float*)d_in[7];
    const float* d3_w   = (const float*)d_in[8];
    const float* d3_b   = (const float*)d_in[9];
    const float* d5_w   = (const float*)d_in[10];
    const float* d5_b   = (const float*)d_in[11];
    const float* proj_w = (const float*)d_in[12];
    float* out = (float*)d_out;

    float *t, *qkv, *y, *Spart, *Npart, *attn;
    cudaGetSymbolAddress((void**)&t,     g_t);
    cudaGetSymbolAddress((void**)&qkv,   g_qkv);
    cudaGetSymbolAddress((void**)&y,     g_y);
    cudaGetSymbolAddress((void**)&Spart, g_Spart);
    cudaGetSymbolAddress((void**)&Npart, g_Npart);
    cudaGetSymbolAddress((void**)&attn,  g_attn);

    // 1) t = pos_w @ x + pos_b   (M=384, K=128, N=hw per batch)
    {
        dim3 grid(HWSZ / 128, TCH / 128, BATCH);
        mma_gemm<<<grid, 256>>>(pos_w, x, pos_b, t,
                                TCH, HWSZ, CIN,
                                (long)CIN * HWSZ, (long)TCH * HWSZ);
    }
    // 2+3) qkv = [gconv3(t); gconv5(t)]
    {
        dim3 grid(64, 192, BATCH);
        gconv_fused_kernel<<<grid, 256>>>(t, qd3_w, qd3_b, qd5_w, qd5_b,
                                          qkv, TCH, QKVCH, 0, 192);
    }
    // 4+5) gram -> softmax -> attn
    {
        dim3 grid(GRAM_NS, 64);
        gram_partial<<<grid, 256>>>(qkv, Spart, Npart);
        softmax_kernel<<<64, 256>>>(Spart, Npart, temp, attn);
    }
    // 6) y[0:128] = attn @ v
    {
        dim3 grid(HWSZ / 256, NH, BATCH);
        attn_apply<<<grid, 256>>>(qkv, attn, y);
    }
    // 7+8) y[128:256] = [gconv3(x); gconv5(x)]
    {
        dim3 grid(64, 64, BATCH);
        gconv_fused_kernel<<<grid, 256>>>(x, d3_w, d3_b, d5_w, d5_b,
                                          y, CIN, YCH, 128, 192);
    }
    // 9) out = proj_w @ y   (M=128, K=256, N=hw per batch)
    {
        dim3 grid(HWSZ / 128, CIN / 128, BATCH);
        mma_gemm<<<grid, 256>>>(proj_w, y, nullptr, out,
                                CIN, HWSZ, YCH,
                                (long)YCH * HWSZ, (long)CIN * HWSZ);
    }
}